// round 1
// baseline (speedup 1.0000x reference)
#include <cuda_runtime.h>

#define NQ      10
#define DIM     1024
#define TSTEPS  10
#define NDATA   1024
#define NTHREADS 512
#define NGATES  (TSTEPS * NQ)

__global__ __launch_bounds__(NTHREADS)
void scramble_kernel(const float* __restrict__ in_re,
                     const float* __restrict__ in_im,
                     const float* __restrict__ phis,
                     const float* __restrict__ gs,
                     float* __restrict__ out)
{
    __shared__ float2 psi[DIM];                 // state (re, im) interleaved
    __shared__ float2 gm[NGATES][4];            // m00, m01, m10, m11 per gate
    __shared__ float2 ph[TSTEPS][NQ + 1];       // diagonal phase by popcount
    __shared__ float  warp_sums[NTHREADS / 32];
    __shared__ float  s_invnorm;

    const int b = blockIdx.x;
    const int t = threadIdx.x;

    // ---- load state, accumulate squared norm ----
    float local = 0.f;
    #pragma unroll
    for (int r = 0; r < 2; r++) {
        int j = t + r * NTHREADS;
        float re = in_re[b * DIM + j];
        float im = in_im[b * DIM + j];
        psi[j] = make_float2(re, im);
        local += re * re + im * im;
    }
    #pragma unroll
    for (int off = 16; off; off >>= 1)
        local += __shfl_xor_sync(0xFFFFFFFFu, local, off);
    if ((t & 31) == 0) warp_sums[t >> 5] = local;

    // ---- precompute all 100 gate matrices (threads 0..99) ----
    if (t < NGATES) {
        int tt = t / NQ, i = t % NQ;
        int base = b * (3 * NQ * TSTEPS) + 3 * NQ * tt;
        float a  = phis[base + i];
        float th = phis[base + NQ + i];
        float bb = phis[base + 2 * NQ + i];
        float c, s, ca, sa, cd, sd;
        sincosf(0.5f * th,        &s,  &c);
        sincosf(0.5f * (a + bb),  &sa, &ca);
        sincosf(0.5f * (a - bb),  &sd, &cd);
        // m00 = c*e^{-i(a+b)/2}; m01 = -s*e^{+i(a-b)/2};
        // m10 = s*e^{-i(a-b)/2}; m11 = c*e^{+i(a+b)/2}
        gm[t][0] = make_float2( c * ca, -c * sa);
        gm[t][1] = make_float2(-s * cd, -s * sd);
        gm[t][2] = make_float2( s * cd, -s * sd);
        gm[t][3] = make_float2( c * ca,  c * sa);
    } else if (t < NGATES + TSTEPS * (NQ + 1)) {
        // ---- precompute diagonal-phase table: exp(-0.5 i * theta * pairsum(k)) ----
        int u  = t - NGATES;
        int tt = u / (NQ + 1);
        int k  = u % (NQ + 1);          // popcount value
        const float inv = 0.15811388300841897f;  // 1/(2*sqrt(10))
        float theta = gs[b * TSTEPS + tt] * inv;
        float zs = 10.f - 2.f * (float)k;
        float ps = 0.5f * (zs * zs - 10.f);
        float sn, cs;
        sincosf(-0.5f * theta * ps, &sn, &cs);
        ph[tt][k] = make_float2(cs, sn);
    }
    __syncthreads();

    if (t == 0) {
        float sum = 0.f;
        #pragma unroll
        for (int w = 0; w < NTHREADS / 32; w++) sum += warp_sums[w];
        s_invnorm = rsqrtf(sum);
    }
    // (s_invnorm consumed only at the end; intervening barriers order it)

    // ---- main loop: 10 steps x (10 gates + diagonal phase) ----
    for (int tt = 0; tt < TSTEPS; tt++) {
        #pragma unroll
        for (int i = 0; i < NQ; i++) {
            const int right = 1 << (NQ - 1 - i);
            const int g = tt * NQ + i;
            // disjoint pairs per thread -> only one barrier per gate
            __syncthreads();
            int idx0 = ((t & ~(right - 1)) << 1) | (t & (right - 1));
            int idx1 = idx0 + right;
            float2 m00 = gm[g][0], m01 = gm[g][1], m10 = gm[g][2], m11 = gm[g][3];
            float2 p0 = psi[idx0], p1 = psi[idx1];
            float2 q0, q1;
            q0.x = m00.x * p0.x - m00.y * p0.y + m01.x * p1.x - m01.y * p1.y;
            q0.y = m00.x * p0.y + m00.y * p0.x + m01.x * p1.y + m01.y * p1.x;
            q1.x = m10.x * p0.x - m10.y * p0.y + m11.x * p1.x - m11.y * p1.y;
            q1.y = m10.x * p0.y + m10.y * p0.x + m11.x * p1.y + m11.y * p1.x;
            psi[idx0] = q0;
            psi[idx1] = q1;
        }
        // diagonal entangling phase (elementwise, popcount-indexed table)
        __syncthreads();
        #pragma unroll
        for (int r = 0; r < 2; r++) {
            int j = t + r * NTHREADS;
            float2 f = ph[tt][__popc(j)];
            float2 p = psi[j];
            psi[j] = make_float2(p.x * f.x - p.y * f.y,
                                 p.x * f.y + p.y * f.x);
        }
    }

    // ---- write out, folding in the (deferred) normalization ----
    __syncthreads();
    float s = s_invnorm;
    #pragma unroll
    for (int r = 0; r < 2; r++) {
        int j = t + r * NTHREADS;
        float2 p = psi[j];
        out[b * DIM + j]               = p.x * s;   // real part
        out[NDATA * DIM + b * DIM + j] = p.y * s;   // imag part
    }
}

extern "C" void kernel_launch(void* const* d_in, const int* in_sizes, int n_in,
                              void* d_out, int out_size)
{
    const float* in_re = (const float*)d_in[0];
    const float* in_im = (const float*)d_in[1];
    const float* phis  = (const float*)d_in[2];
    const float* gs    = (const float*)d_in[3];
    float* out = (float*)d_out;
    scramble_kernel<<<NDATA, NTHREADS>>>(in_re, in_im, phis, gs, out);
}

// round 2
// speedup vs baseline: 1.9226x; 1.9226x over previous
#include <cuda_runtime.h>

#define NQ       10
#define DIM      1024
#define TSTEPS   10
#define NDATA    1024
#define WPB      2                 // warps per block (1 sample per warp)
#define NTHREADS (WPB * 32)
#define NGATES   (TSTEPS * NQ)

__global__ __launch_bounds__(NTHREADS)
void scramble_kernel(const float* __restrict__ in_re,
                     const float* __restrict__ in_im,
                     const float* __restrict__ phis,
                     const float* __restrict__ gs,
                     float* __restrict__ out)
{
    // per-warp scratch: gate matrices (100 x 2 float4) + phase tables (10 x 11 float2)
    __shared__ float4 s_gm[WPB][NGATES][2];
    __shared__ float2 s_ph[WPB][TSTEPS * (NQ + 1)];

    const int w    = threadIdx.x >> 5;
    const int lane = threadIdx.x & 31;
    const int b    = blockIdx.x * WPB + w;

    // ---- precompute all 100 gate matrices (lanes split the work) ----
    for (int g = lane; g < NGATES; g += 32) {
        int tt = g / NQ, i = g - tt * NQ;
        int base = b * (3 * NQ * TSTEPS) + 3 * NQ * tt;
        float a  = phis[base + i];
        float th = phis[base + NQ + i];
        float bb = phis[base + 2 * NQ + i];
        float c, s, ca, sa, cd, sd;
        __sincosf(0.5f * th,       &s,  &c);
        __sincosf(0.5f * (a + bb), &sa, &ca);
        __sincosf(0.5f * (a - bb), &sd, &cd);
        // m00 = c e^{-i(a+b)/2}, m01 = -s e^{i(a-b)/2}
        // m10 = s e^{-i(a-b)/2}, m11 = c e^{i(a+b)/2}
        s_gm[w][g][0] = make_float4( c * ca, -c * sa, -s * cd, -s * sd); // m00, m01
        s_gm[w][g][1] = make_float4( s * cd, -s * sd,  c * ca,  c * sa); // m10, m11
    }
    // ---- precompute diagonal phase tables: exp(-0.5 i theta * pairsum(popc)) ----
    for (int u = lane; u < TSTEPS * (NQ + 1); u += 32) {
        int tt = u / (NQ + 1), k = u - tt * (NQ + 1);
        const float inv = 0.15811388300841897f;   // 1/(2*sqrt(10))
        float theta = gs[b * TSTEPS + tt] * inv;
        float zs = 10.f - 2.f * (float)k;
        float ps = 0.5f * (zs * zs - 10.f);
        float sn, cs;
        __sincosf(-0.5f * theta * ps, &sn, &cs);
        s_ph[w][u] = make_float2(cs, sn);
    }

    // ---- load state into registers: j = (r<<5) | lane ----
    float2 psi[32];
    float nrm = 0.f;
    #pragma unroll
    for (int r = 0; r < 32; r++) {
        int j = (r << 5) | lane;
        float re = in_re[b * DIM + j];
        float im = in_im[b * DIM + j];
        psi[r] = make_float2(re, im);
        nrm += re * re + im * im;
    }
    #pragma unroll
    for (int off = 16; off; off >>= 1)
        nrm += __shfl_xor_sync(0xFFFFFFFFu, nrm, off);
    const float invn = rsqrtf(nrm);

    __syncwarp();
    const int pl = __popc(lane);

    // ---- main loop: no __syncthreads anywhere ----
    for (int tt = 0; tt < TSTEPS; tt++) {
        // qubits 0..4: register-local pairs (stride in r-space)
        #pragma unroll
        for (int i = 0; i < 5; i++) {
            const int mask = 1 << (4 - i);
            float4 g0 = s_gm[w][tt * NQ + i][0];
            float4 g1 = s_gm[w][tt * NQ + i][1];
            #pragma unroll
            for (int rr = 0; rr < 16; rr++) {
                int r0 = ((rr & ~(mask - 1)) << 1) | (rr & (mask - 1));
                int r1 = r0 | mask;
                float2 p0 = psi[r0], p1 = psi[r1];
                psi[r0].x = g0.x * p0.x - g0.y * p0.y + g0.z * p1.x - g0.w * p1.y;
                psi[r0].y = g0.x * p0.y + g0.y * p0.x + g0.z * p1.y + g0.w * p1.x;
                psi[r1].x = g1.x * p0.x - g1.y * p0.y + g1.z * p1.x - g1.w * p1.y;
                psi[r1].y = g1.x * p0.y + g1.y * p0.x + g1.z * p1.y + g1.w * p1.x;
            }
        }
        // qubits 5..9: lane-bit pairs via warp shuffle
        #pragma unroll
        for (int i = 5; i < 10; i++) {
            const int m = 1 << (9 - i);
            float4 g0 = s_gm[w][tt * NQ + i][0];
            float4 g1 = s_gm[w][tt * NQ + i][1];
            const bool hi = (lane & m) != 0;
            // new_own = A*own + B*other  (row selected once per gate)
            float Ax = hi ? g1.z : g0.x, Ay = hi ? g1.w : g0.y;
            float Bx = hi ? g1.x : g0.z, By = hi ? g1.y : g0.w;
            #pragma unroll
            for (int r = 0; r < 32; r++) {
                float ox = __shfl_xor_sync(0xFFFFFFFFu, psi[r].x, m);
                float oy = __shfl_xor_sync(0xFFFFFFFFu, psi[r].y, m);
                float nx = Ax * psi[r].x - Ay * psi[r].y + Bx * ox - By * oy;
                float ny = Ax * psi[r].y + Ay * psi[r].x + Bx * oy + By * ox;
                psi[r] = make_float2(nx, ny);
            }
        }
        // diagonal entangling phase (popc(r) is a compile-time constant here)
        #pragma unroll
        for (int r = 0; r < 32; r++) {
            float2 f = s_ph[w][tt * (NQ + 1) + pl + __popc(r)];
            float px = psi[r].x, py = psi[r].y;
            psi[r].x = px * f.x - py * f.y;
            psi[r].y = px * f.y + py * f.x;
        }
    }

    // ---- store with deferred normalization ----
    #pragma unroll
    for (int r = 0; r < 32; r++) {
        int j = (r << 5) | lane;
        float2 p = psi[r];
        out[b * DIM + j]               = p.x * invn;
        out[NDATA * DIM + b * DIM + j] = p.y * invn;
    }
}

extern "C" void kernel_launch(void* const* d_in, const int* in_sizes, int n_in,
                              void* d_out, int out_size)
{
    const float* in_re = (const float*)d_in[0];
    const float* in_im = (const float*)d_in[1];
    const float* phis  = (const float*)d_in[2];
    const float* gs    = (const float*)d_in[3];
    float* out = (float*)d_out;
    scramble_kernel<<<NDATA / WPB, NTHREADS>>>(in_re, in_im, phis, gs, out);
}

// round 3
// speedup vs baseline: 2.0880x; 1.0860x over previous
#include <cuda_runtime.h>

#define NQ      10
#define DIM     1024
#define TSTEPS  10
#define NDATA   1024
#define NGATES  (TSTEPS * NQ)
#define NTHREADS 64               // 2 warps = 1 sample, 16 amplitudes/thread

typedef unsigned long long u64;

// ---- packed f32x2 helpers (FFMA2 only reachable via PTX) ----
__device__ __forceinline__ u64 pk(float x, float y) {
    u64 u; asm("mov.b64 %0, {%1,%2};" : "=l"(u) : "f"(x), "f"(y)); return u;
}
__device__ __forceinline__ void upk(u64 u, float &x, float &y) {
    asm("mov.b64 {%0,%1}, %2;" : "=f"(x), "=f"(y) : "l"(u));
}
__device__ __forceinline__ u64 swp(u64 u) { float x, y; upk(u, x, y); return pk(y, x); }
__device__ __forceinline__ u64 ffma2(u64 a, u64 b, u64 c) {
    u64 d; asm("fma.rn.f32x2 %0, %1, %2, %3;" : "=l"(d) : "l"(a), "l"(b), "l"(c)); return d;
}
__device__ __forceinline__ u64 fmul2(u64 a, u64 b) {
    u64 d; asm("mul.rn.f32x2 %0, %1, %2;" : "=l"(d) : "l"(a), "l"(b)); return d;
}
// coefficient float4 (m.x, m.x, -m.y, m.y) -> packed A, B
__device__ __forceinline__ void ldc(float4 v, u64 &A, u64 &B) {
    A = pk(v.x, v.y); B = pk(v.z, v.w);
}
// complex multiply-accumulate: q = m*p  with A=(mx,mx), B=(-my,my)
// q = A (x) p + B (x) swap(p)

__global__ __launch_bounds__(NTHREADS)
void scramble_kernel(const float* __restrict__ in_re,
                     const float* __restrict__ in_im,
                     const float* __restrict__ phis,
                     const float* __restrict__ gs,
                     float* __restrict__ out)
{
    __shared__ float4 s_gm[NGATES][4];          // per element: (mx,mx,-my,my)
    __shared__ float4 s_ph[TSTEPS * (NQ + 1)];  // (c,c,-s,s)
    __shared__ u64    s_x[DIM];                 // cross-warp exchange buffer
    __shared__ float  s_nrm[2];

    const int tid  = threadIdx.x;
    const int w    = tid >> 5;                  // warp = high bit of j (qubit 0)
    const int lane = tid & 31;
    const int b    = blockIdx.x;

    // ---- precompute 100 gate matrices as packed-coefficient float4s ----
    for (int g = tid; g < NGATES; g += NTHREADS) {
        int tt = g / NQ, i = g - tt * NQ;
        int base = b * (3 * NQ * TSTEPS) + 3 * NQ * tt;
        float a  = phis[base + i];
        float th = phis[base + NQ + i];
        float bb = phis[base + 2 * NQ + i];
        float c, s, ca, sa, cd, sd;
        __sincosf(0.5f * th,       &s,  &c);
        __sincosf(0.5f * (a + bb), &sa, &ca);
        __sincosf(0.5f * (a - bb), &sd, &cd);
        // m00=(c ca, -c sa)  m01=(-s cd, -s sd)  m10=(s cd, -s sd)  m11=(c ca, c sa)
        s_gm[g][0] = make_float4( c * ca,  c * ca,  c * sa, -c * sa);
        s_gm[g][1] = make_float4(-s * cd, -s * cd,  s * sd, -s * sd);
        s_gm[g][2] = make_float4( s * cd,  s * cd,  s * sd, -s * sd);
        s_gm[g][3] = make_float4( c * ca,  c * ca, -c * sa,  c * sa);
    }
    // ---- diagonal phase tables ----
    for (int u = tid; u < TSTEPS * (NQ + 1); u += NTHREADS) {
        int tt = u / (NQ + 1), k = u - tt * (NQ + 1);
        const float inv = 0.15811388300841897f;   // 1/(2*sqrt(10))
        float theta = gs[b * TSTEPS + tt] * inv;
        float zs = 10.f - 2.f * (float)k;
        float ps = 0.5f * (zs * zs - 10.f);
        float sn, cs;
        __sincosf(-0.5f * theta * ps, &sn, &cs);
        s_ph[u] = make_float4(cs, cs, -sn, sn);
    }

    // ---- load 16 amplitudes: j = (w<<9)|(r<<5)|lane ----
    u64 psi[16];
    float nrm = 0.f;
    #pragma unroll
    for (int r = 0; r < 16; r++) {
        int j = (w << 9) | (r << 5) | lane;
        float re = in_re[b * DIM + j];
        float im = in_im[b * DIM + j];
        psi[r] = pk(re, im);
        nrm += re * re + im * im;
    }
    #pragma unroll
    for (int off = 16; off; off >>= 1)
        nrm += __shfl_xor_sync(0xFFFFFFFFu, nrm, off);
    if (lane == 0) s_nrm[w] = nrm;
    __syncthreads();
    const float invn = rsqrtf(s_nrm[0] + s_nrm[1]);
    const int pb = __popc(lane) + w;   // popcount contribution of lane + warp bit

    for (int tt = 0; tt < TSTEPS; tt++) {
        // ---- qubit 0 (stride 512): cross-warp gate via smem ----
        __syncthreads();                       // prior step's reads done
        #pragma unroll
        for (int r = 0; r < 16; r++)
            s_x[(w << 9) | (r << 5) | lane] = psi[r];
        __syncthreads();
        {
            float4 own4 = s_gm[tt * NQ][w ? 3 : 0];   // m11 : m00
            float4 oth4 = s_gm[tt * NQ][w ? 2 : 1];   // m10 : m01
            u64 A, Ab, B, Bb;
            ldc(own4, A, Ab); ldc(oth4, B, Bb);
            const int pbase = ((1 - w) << 9) | lane;
            #pragma unroll
            for (int r = 0; r < 16; r++) {
                u64 oth = s_x[pbase | (r << 5)];
                u64 own = psi[r];
                psi[r] = ffma2(Bb, swp(oth),
                         ffma2(B,  oth,
                         ffma2(Ab, swp(own),
                         fmul2(A,  own))));
            }
        }
        // ---- qubits 1..4: register-local pairs ----
        #pragma unroll
        for (int i = 1; i < 5; i++) {
            const int m = 1 << (4 - i);
            const float4* gg = s_gm[tt * NQ + i];
            u64 c00A, c00B, c01A, c01B, c10A, c10B, c11A, c11B;
            ldc(gg[0], c00A, c00B); ldc(gg[1], c01A, c01B);
            ldc(gg[2], c10A, c10B); ldc(gg[3], c11A, c11B);
            #pragma unroll
            for (int rr = 0; rr < 8; rr++) {
                int r0 = ((rr & ~(m - 1)) << 1) | (rr & (m - 1));
                int r1 = r0 | m;
                u64 p0 = psi[r0], p1 = psi[r1];
                u64 p0s = swp(p0), p1s = swp(p1);
                psi[r0] = ffma2(c01B, p1s, ffma2(c01A, p1,
                          ffma2(c00B, p0s, fmul2(c00A, p0))));
                psi[r1] = ffma2(c11B, p1s, ffma2(c11A, p1,
                          ffma2(c10B, p0s, fmul2(c10A, p0))));
            }
        }
        // ---- qubits 5..9: lane-bit pairs via warp shuffle ----
        #pragma unroll
        for (int i = 5; i < 10; i++) {
            const int m = 1 << (9 - i);
            const float4* gg = s_gm[tt * NQ + i];
            const bool hi = (lane & m) != 0;
            float4 own4 = hi ? gg[3] : gg[0];
            float4 oth4 = hi ? gg[2] : gg[1];
            u64 A, Ab, B, Bb;
            ldc(own4, A, Ab); ldc(oth4, B, Bb);
            #pragma unroll
            for (int r = 0; r < 16; r++) {
                float x, y; upk(psi[r], x, y);
                float ox = __shfl_xor_sync(0xFFFFFFFFu, x, m);
                float oy = __shfl_xor_sync(0xFFFFFFFFu, y, m);
                u64 oth = pk(ox, oy);
                psi[r] = ffma2(Bb, pk(oy, ox),
                         ffma2(B,  oth,
                         ffma2(Ab, pk(y, x),
                         fmul2(A,  psi[r]))));
            }
        }
        // ---- diagonal entangling phase ----
        #pragma unroll
        for (int r = 0; r < 16; r++) {
            float4 f4 = s_ph[tt * (NQ + 1) + pb + __popc(r)];
            u64 fA, fB; ldc(f4, fA, fB);
            psi[r] = ffma2(fB, swp(psi[r]), fmul2(fA, psi[r]));
        }
    }

    // ---- store with deferred normalization ----
    #pragma unroll
    for (int r = 0; r < 16; r++) {
        int j = (w << 9) | (r << 5) | lane;
        float x, y; upk(psi[r], x, y);
        out[b * DIM + j]               = x * invn;
        out[NDATA * DIM + b * DIM + j] = y * invn;
    }
}

extern "C" void kernel_launch(void* const* d_in, const int* in_sizes, int n_in,
                              void* d_out, int out_size)
{
    const float* in_re = (const float*)d_in[0];
    const float* in_im = (const float*)d_in[1];
    const float* phis  = (const float*)d_in[2];
    const float* gs    = (const float*)d_in[3];
    float* out = (float*)d_out;
    scramble_kernel<<<NDATA, NTHREADS>>>(in_re, in_im, phis, gs, out);
}